// round 1
// baseline (speedup 1.0000x reference)
#include <cuda_runtime.h>

// Problem constants
#define Bc 4
#define Tc 2048
#define Ec 1024
#define Hc 16
#define Dc 64
#define MROWS (Bc * Tc)   // 8192

// Static scratch (no allocation allowed)
__device__ float g_q[(size_t)Bc * Hc * Tc * Dc];     // 32MB  [B,H,T,D]
__device__ float g_k[(size_t)Bc * Hc * Tc * Dc];     // 32MB
__device__ float g_v[(size_t)Bc * Hc * Tc * Dc];     // 32MB
__device__ float g_ctx[(size_t)MROWS * Ec];          // 32MB  [B*T, E]

// ---------------------------------------------------------------------------
// SGEMM: C[M,N] = A[M,K] @ W[K,N] + bias[N]
// 128x128 block tile, BK=8, 256 threads, 8x8 micro-tile, register prefetch.
// MODE 0: A = x, epilogue scatters into g_q/g_k/g_v ([B,H,T,D] layout)
// MODE 1: A = g_ctx, epilogue writes C (d_out) row-major
// ---------------------------------------------------------------------------
template <int MODE>
__global__ __launch_bounds__(256, 2) void sgemm_kernel(
    const float* __restrict__ A, const float* __restrict__ W,
    const float* __restrict__ bias, float* __restrict__ C,
    int M, int N, int K)
{
    __shared__ float As[8][128];
    __shared__ float Bs[8][128];

    const float* Ap = (MODE == 0) ? A : (const float*)g_ctx;

    int tid   = threadIdx.x;
    int mBase = blockIdx.y * 128;
    int nBase = blockIdx.x * 128;

    int aRow = tid >> 1;
    int aCol = (tid & 1) * 4;
    int bRow = tid >> 5;
    int bCol = (tid & 31) * 4;

    const float* aPtr = Ap + (size_t)(mBase + aRow) * K + aCol;
    const float* bPtr = W + (size_t)bRow * N + nBase + bCol;

    float4 aReg = *(const float4*)aPtr;
    float4 bReg = *(const float4*)bPtr;

    float acc[8][8] = {};
    int tx = tid & 15, ty = tid >> 4;

    for (int k0 = 0; k0 < K; k0 += 8) {
        As[aCol + 0][aRow] = aReg.x;
        As[aCol + 1][aRow] = aReg.y;
        As[aCol + 2][aRow] = aReg.z;
        As[aCol + 3][aRow] = aReg.w;
        *(float4*)&Bs[bRow][bCol] = bReg;
        __syncthreads();

        if (k0 + 8 < K) {
            aReg = *(const float4*)(aPtr + k0 + 8);
            bReg = *(const float4*)(bPtr + (size_t)(k0 + 8) * N);
        }

        #pragma unroll
        for (int kk = 0; kk < 8; kk++) {
            float4 a0 = *(const float4*)&As[kk][ty * 4];
            float4 a1 = *(const float4*)&As[kk][64 + ty * 4];
            float4 b0 = *(const float4*)&Bs[kk][tx * 4];
            float4 b1 = *(const float4*)&Bs[kk][64 + tx * 4];
            float av[8] = {a0.x, a0.y, a0.z, a0.w, a1.x, a1.y, a1.z, a1.w};
            float bv[8] = {b0.x, b0.y, b0.z, b0.w, b1.x, b1.y, b1.z, b1.w};
            #pragma unroll
            for (int i = 0; i < 8; i++)
                #pragma unroll
                for (int j = 0; j < 8; j++)
                    acc[i][j] = fmaf(av[i], bv[j], acc[i][j]);
        }
        __syncthreads();
    }

    #pragma unroll
    for (int i = 0; i < 8; i++) {
        int row = mBase + ((i < 4) ? (ty * 4 + i) : (64 + ty * 4 + (i - 4)));
        #pragma unroll
        for (int j = 0; j < 8; j++) {
            int col = nBase + ((j < 4) ? (tx * 4 + j) : (64 + tx * 4 + (j - 4)));
            float v = acc[i][j] + bias[col];
            if (MODE == 0) {
                int part = col >> 10;           // 0=q, 1=k, 2=v
                int e    = col & 1023;
                int h    = e >> 6;
                int d    = e & 63;
                int b    = row >> 11;
                int t    = row & 2047;
                float* dst = (part == 0) ? g_q : (part == 1) ? g_k : g_v;
                dst[(((size_t)b * Hc + h) * Tc + t) * Dc + d] = v;
            } else {
                C[(size_t)row * N + col] = v;
            }
        }
    }
}

// ---------------------------------------------------------------------------
// Flash attention, fp32. One block per (bh, q-tile of 64). 256 threads.
// Thread (r = tid>>2, c = tid&3): owns query row r.
//   scores: keys {kk*4+c : kk in 0..15}   (interleaved -> conflict-free Ks reads)
//   output: dims  {j*16 + c*4 .. +3 : j in 0..3}
// Streaming softmax with per-quad shuffle reductions (lanes 4r..4r+3).
// ---------------------------------------------------------------------------
#define QS_STRIDE 68
#define PS_STRIDE 65
#define FLASH_SMEM_FLOATS (64 * QS_STRIDE * 2 + 64 * PS_STRIDE + 64 * 64)
#define FLASH_SMEM_BYTES (FLASH_SMEM_FLOATS * 4)

__global__ __launch_bounds__(256) void flash_kernel()
{
    extern __shared__ float sm[];
    float* Qs = sm;                                   // [64][68]
    float* Ks = sm + 64 * QS_STRIDE;                  // [64][68]
    float* Ps = sm + 2 * 64 * QS_STRIDE;              // [64][65]
    float* Vs = sm + 2 * 64 * QS_STRIDE + 64 * PS_STRIDE; // [64][64]

    int tid = threadIdx.x;
    int r = tid >> 2;
    int c = tid & 3;
    int bh = blockIdx.y;
    int qt = blockIdx.x;
    int q0 = qt * 64;
    size_t base = (size_t)bh * Tc;

    // Load Q tile, pre-scaled by 1/sqrt(D)=0.125
    {
        int col = c * 16;
        const float4* src = (const float4*)(g_q + (base + q0 + r) * Dc + col);
        #pragma unroll
        for (int i = 0; i < 4; i++) {
            float4 f = src[i];
            f.x *= 0.125f; f.y *= 0.125f; f.z *= 0.125f; f.w *= 0.125f;
            *(float4*)&Qs[r * QS_STRIDE + col + i * 4] = f;
        }
    }

    float m_prev = -1e30f, lsum = 0.f;
    float4 o0 = make_float4(0.f, 0.f, 0.f, 0.f), o1 = o0, o2 = o0, o3 = o0;

    for (int kt = 0; kt <= qt; kt++) {
        __syncthreads();   // covers Q-load barrier on first iter, Vs reuse after
        {
            int col = c * 16;
            const float4* ksrc = (const float4*)(g_k + (base + kt * 64 + r) * Dc + col);
            const float4* vsrc = (const float4*)(g_v + (base + kt * 64 + r) * Dc + col);
            #pragma unroll
            for (int i = 0; i < 4; i++) {
                *(float4*)&Ks[r * QS_STRIDE + col + i * 4] = ksrc[i];
                *(float4*)&Vs[r * 64 + col + i * 4] = vsrc[i];
            }
        }
        __syncthreads();

        // Scores for this thread's 16 keys
        float s[16];
        #pragma unroll
        for (int kk = 0; kk < 16; kk++) s[kk] = 0.f;
        #pragma unroll
        for (int d4 = 0; d4 < 16; d4++) {
            float4 q4 = *(const float4*)&Qs[r * QS_STRIDE + d4 * 4];
            #pragma unroll
            for (int kk = 0; kk < 16; kk++) {
                float4 k4 = *(const float4*)&Ks[(kk * 4 + c) * QS_STRIDE + d4 * 4];
                s[kk] = fmaf(q4.x, k4.x,
                        fmaf(q4.y, k4.y,
                        fmaf(q4.z, k4.z,
                        fmaf(q4.w, k4.w, s[kk]))));
            }
        }
        if (kt == qt) {   // diagonal tile: causal mask (s0 == q0)
            #pragma unroll
            for (int kk = 0; kk < 16; kk++)
                if (kk * 4 + c > r) s[kk] = -1e30f;
        }

        // Row max across 64 keys (16 local + quad shuffle)
        float mt = s[0];
        #pragma unroll
        for (int kk = 1; kk < 16; kk++) mt = fmaxf(mt, s[kk]);
        mt = fmaxf(mt, __shfl_xor_sync(0xffffffffu, mt, 1));
        mt = fmaxf(mt, __shfl_xor_sync(0xffffffffu, mt, 2));
        float m_new = fmaxf(m_prev, mt);
        float alpha = __expf(m_prev - m_new);

        float rs = 0.f;
        #pragma unroll
        for (int kk = 0; kk < 16; kk++) {
            float p = __expf(s[kk] - m_new);
            Ps[r * PS_STRIDE + kk * 4 + c] = p;
            rs += p;
        }
        rs += __shfl_xor_sync(0xffffffffu, rs, 1);
        rs += __shfl_xor_sync(0xffffffffu, rs, 2);
        lsum = lsum * alpha + rs;
        m_prev = m_new;

        o0.x *= alpha; o0.y *= alpha; o0.z *= alpha; o0.w *= alpha;
        o1.x *= alpha; o1.y *= alpha; o1.z *= alpha; o1.w *= alpha;
        o2.x *= alpha; o2.y *= alpha; o2.z *= alpha; o2.w *= alpha;
        o3.x *= alpha; o3.y *= alpha; o3.z *= alpha; o3.w *= alpha;
        __syncwarp();    // Ps written/read within the same warp's quads

        // O += P @ V  (this thread: row r, dims j*16 + c*4)
        #pragma unroll 16
        for (int k = 0; k < 64; k++) {
            float pv = Ps[r * PS_STRIDE + k];
            float4 v0 = *(const float4*)&Vs[k * 64 + 0  + c * 4];
            float4 v1 = *(const float4*)&Vs[k * 64 + 16 + c * 4];
            float4 v2 = *(const float4*)&Vs[k * 64 + 32 + c * 4];
            float4 v3 = *(const float4*)&Vs[k * 64 + 48 + c * 4];
            o0.x = fmaf(pv, v0.x, o0.x); o0.y = fmaf(pv, v0.y, o0.y);
            o0.z = fmaf(pv, v0.z, o0.z); o0.w = fmaf(pv, v0.w, o0.w);
            o1.x = fmaf(pv, v1.x, o1.x); o1.y = fmaf(pv, v1.y, o1.y);
            o1.z = fmaf(pv, v1.z, o1.z); o1.w = fmaf(pv, v1.w, o1.w);
            o2.x = fmaf(pv, v2.x, o2.x); o2.y = fmaf(pv, v2.y, o2.y);
            o2.z = fmaf(pv, v2.z, o2.z); o2.w = fmaf(pv, v2.w, o2.w);
            o3.x = fmaf(pv, v3.x, o3.x); o3.y = fmaf(pv, v3.y, o3.y);
            o3.z = fmaf(pv, v3.z, o3.z); o3.w = fmaf(pv, v3.w, o3.w);
        }
    }

    float inv = 1.f / lsum;
    int b = bh >> 4, h = bh & 15;
    float* outp = g_ctx + ((size_t)(b * Tc + q0 + r)) * Ec + h * Dc;
    o0.x *= inv; o0.y *= inv; o0.z *= inv; o0.w *= inv;
    o1.x *= inv; o1.y *= inv; o1.z *= inv; o1.w *= inv;
    o2.x *= inv; o2.y *= inv; o2.z *= inv; o2.w *= inv;
    o3.x *= inv; o3.y *= inv; o3.z *= inv; o3.w *= inv;
    *(float4*)&outp[0  + c * 4] = o0;
    *(float4*)&outp[16 + c * 4] = o1;
    *(float4*)&outp[32 + c * 4] = o2;
    *(float4*)&outp[48 + c * 4] = o3;
}

// ---------------------------------------------------------------------------
extern "C" void kernel_launch(void* const* d_in, const int* in_sizes, int n_in,
                              void* d_out, int out_size)
{
    const float* x     = (const float*)d_in[0];   // [4,2048,1024]
    const float* w_qkv = (const float*)d_in[1];   // [1024,3072]
    const float* b_qkv = (const float*)d_in[2];   // [3072]
    const float* w_out = (const float*)d_in[3];   // [1024,1024]
    const float* b_out = (const float*)d_in[4];   // [1024]
    float* out = (float*)d_out;                   // [4,2048,1024]

    (void)in_sizes; (void)n_in; (void)out_size;

    cudaFuncSetAttribute((const void*)flash_kernel,
                         cudaFuncAttributeMaxDynamicSharedMemorySize,
                         FLASH_SMEM_BYTES);

    // Stage 1: QKV projection -> g_q/g_k/g_v in [B,H,T,D]
    {
        dim3 grid(3 * Ec / 128, MROWS / 128);   // (24, 64)
        sgemm_kernel<0><<<grid, 256>>>(x, w_qkv, b_qkv, nullptr,
                                       MROWS, 3 * Ec, Ec);
    }
    // Stage 2: causal flash attention -> g_ctx in [B*T, E]
    {
        dim3 grid(Tc / 64, Bc * Hc);            // (32, 64)
        flash_kernel<<<grid, 256, FLASH_SMEM_BYTES>>>();
    }
    // Stage 3: output projection -> d_out
    {
        dim3 grid(Ec / 128, MROWS / 128);       // (8, 64)
        sgemm_kernel<1><<<grid, 256>>>(nullptr, w_out, b_out, out,
                                       MROWS, Ec, Ec);
    }
}

// round 4
// speedup vs baseline: 1.2717x; 1.2717x over previous
#include <cuda_runtime.h>
#include <cstdint>

// Problem constants
#define Bc 4
#define Tc 2048
#define Ec 1024
#define Hc 16
#define Dc 64
#define MROWS (Bc * Tc)   // 8192

// Static scratch (no allocation allowed)
__device__ float g_q[(size_t)Bc * Hc * Tc * Dc];     // 32MB  [B,H,T,D]
__device__ float g_k[(size_t)Bc * Hc * Tc * Dc];     // 32MB
__device__ float g_v[(size_t)Bc * Hc * Tc * Dc];     // 32MB
__device__ float g_ctx[(size_t)MROWS * Ec];          // 32MB  [B*T, E] (tf32-rounded)
__device__ float g_xr[(size_t)MROWS * Ec];           // 32MB  x rounded to tf32
__device__ float g_wqkvT[(size_t)3 * Ec * Ec];       // 12MB  [3E, E] tf32
__device__ float g_woutT[(size_t)Ec * Ec];           // 4MB   [E, E] tf32

// ---------------------------------------------------------------------------
// helpers
// ---------------------------------------------------------------------------
__device__ __forceinline__ uint32_t smem_u32(const void* p) {
    uint32_t a;
    asm("{ .reg .u64 t; cvta.to.shared.u64 t, %1; cvt.u32.u64 %0, t; }"
        : "=r"(a) : "l"(p));
    return a;
}
__device__ __forceinline__ float to_tf32(float x) {
    uint32_t r;
    asm("cvt.rna.tf32.f32 %0, %1;" : "=r"(r) : "f"(x));
    return __uint_as_float(r);
}
__device__ __forceinline__ void cp16(uint32_t saddr, const float* g) {
    asm volatile("cp.async.cg.shared.global [%0], [%1], 16;"
                 :: "r"(saddr), "l"(__cvta_generic_to_global(g)) : "memory");
}
__device__ __forceinline__ void cp_commit() {
    asm volatile("cp.async.commit_group;" ::: "memory");
}
template <int N>
__device__ __forceinline__ void cp_wait() {
    asm volatile("cp.async.wait_group %0;" :: "n"(N) : "memory");
}

// m16n8k8 tf32 MMA, fp32 accumulate (baseline PTX, compiles for compute_103)
__device__ __forceinline__ void mma168(float* c, const uint32_t* a, const uint32_t* b) {
    asm volatile(
        "mma.sync.aligned.m16n8k8.row.col.f32.tf32.tf32.f32 "
        "{%0,%1,%2,%3}, {%4,%5,%6,%7}, {%8,%9}, {%0,%1,%2,%3};"
        : "+f"(c[0]), "+f"(c[1]), "+f"(c[2]), "+f"(c[3])
        : "r"(a[0]), "r"(a[1]), "r"(a[2]), "r"(a[3]), "r"(b[0]), "r"(b[1]));
}

// ---------------------------------------------------------------------------
// tc_gemm: C[M,N] = A[M,K] @ Bt[N,K]^T + bias   (tf32 mma.sync)
// 128x128 block tile, BK=16, 256 threads (8 warps, 2Mx4N), warp tile 64x32.
// Both operands in smem as [row128][stride 20] -> conflict-free frag loads.
// MODE 0: epilogue scatters into g_q/g_k/g_v ([B,H,T,D]);  MODE 1: row-major C.
// ---------------------------------------------------------------------------
#define BK 16
#define SA 20   // padded smem stride in floats (20*4=80B; 20g mod 32 distinct)

template <int MODE>
__global__ __launch_bounds__(256) void tc_gemm(
    const float* __restrict__ A, const float* __restrict__ Bt,
    const float* __restrict__ bias, float* __restrict__ C,
    int M, int N, int K)
{
    __shared__ float smA[2][128 * SA];
    __shared__ float smB[2][128 * SA];

    int tid = threadIdx.x;
    int lane = tid & 31;
    int warp = tid >> 5;
    int warpM = warp >> 2;   // 0..1
    int warpN = warp & 3;    // 0..3
    int g  = lane >> 2;      // groupID 0..7
    int tg = lane & 3;       // thread-in-group 0..3

    int mBase = blockIdx.y * 128;
    int nBase = blockIdx.x * 128;
    const int KT = K >> 4;   // BK=16

    uint32_t sA[2] = { smem_u32(&smA[0][0]), smem_u32(&smA[1][0]) };
    uint32_t sB[2] = { smem_u32(&smB[0][0]), smem_u32(&smB[1][0]) };

    // tile loader: 512 chunks per operand (128 rows x 4 float4), 4 per thread
    auto load_tile = [&](int p, int kt) {
        #pragma unroll
        for (int i = 0; i < 4; i++) {
            int idx = tid + i * 256;          // 0..1023
            int row = (idx >> 2) & 127;
            int seg = idx & 3;
            if (idx < 512)
                cp16(sA[p] + row * (SA * 4) + seg * 16,
                     A + (size_t)(mBase + row) * K + kt * BK + seg * 4);
            else
                cp16(sB[p] + row * (SA * 4) + seg * 16,
                     Bt + (size_t)(nBase + row) * K + kt * BK + seg * 4);
        }
        cp_commit();
    };

    float acc[4][4][4] = {};

    load_tile(0, 0);
    load_tile(1, 1);

    for (int kt = 0; kt < KT; kt++) {
        int p = kt & 1;
        if (kt + 1 < KT) cp_wait<1>(); else cp_wait<0>();
        __syncthreads();

        #pragma unroll
        for (int ks = 0; ks < 2; ks++) {
            uint32_t a[4][4], b[4][2];
            const float* Ab = &smA[p][(warpM * 64 + g) * SA + ks * 8 + tg];
            #pragma unroll
            for (int i = 0; i < 4; i++) {
                a[i][0] = __float_as_uint(Ab[(i * 16) * SA]);
                a[i][1] = __float_as_uint(Ab[(i * 16 + 8) * SA]);
                a[i][2] = __float_as_uint(Ab[(i * 16) * SA + 4]);
                a[i][3] = __float_as_uint(Ab[(i * 16 + 8) * SA + 4]);
            }
            const float* Bb = &smB[p][(warpN * 32 + g) * SA + ks * 8 + tg];
            #pragma unroll
            for (int j = 0; j < 4; j++) {
                b[j][0] = __float_as_uint(Bb[(j * 8) * SA]);
                b[j][1] = __float_as_uint(Bb[(j * 8) * SA + 4]);
            }
            #pragma unroll
            for (int i = 0; i < 4; i++)
                #pragma unroll
                for (int j = 0; j < 4; j++)
                    mma168(acc[i][j], a[i], b[j]);
        }
        __syncthreads();

        if (kt + 2 < KT) load_tile(p, kt + 2);
    }

    // epilogue: c0,c1 at (row, col..col+1), c2,c3 at (row+8, col..col+1)
    #pragma unroll
    for (int i = 0; i < 4; i++) {
        #pragma unroll
        for (int j = 0; j < 4; j++) {
            int row = mBase + warpM * 64 + i * 16 + g;
            int col = nBase + warpN * 32 + j * 8 + 2 * tg;
            float2 bb = *(const float2*)&bias[col];
            float2 v0 = make_float2(acc[i][j][0] + bb.x, acc[i][j][1] + bb.y);
            float2 v1 = make_float2(acc[i][j][2] + bb.x, acc[i][j][3] + bb.y);
            if (MODE == 0) {
                int part = col >> 10;
                int e = col & 1023;
                int h = e >> 6;
                int d = e & 63;      // even, d+1 same head
                float* base = ((part == 0) ? g_q : (part == 1) ? g_k : g_v);
                int b0 = row >> 11, t0 = row & 2047;
                *(float2*)&base[(((size_t)b0 * Hc + h) * Tc + t0) * Dc + d] = v0;
                int r1 = row + 8;
                int b1 = r1 >> 11, t1 = r1 & 2047;
                *(float2*)&base[(((size_t)b1 * Hc + h) * Tc + t1) * Dc + d] = v1;
            } else {
                *(float2*)&C[(size_t)row * N + col] = v0;
                *(float2*)&C[(size_t)(row + 8) * N + col] = v1;
            }
        }
    }
}

// ---------------------------------------------------------------------------
// pre-pass: tf32 rounding / transpose+round
// ---------------------------------------------------------------------------
__global__ void round_tf32_vec(const float* __restrict__ in, float* __restrict__ out, int n4)
{
    int i = blockIdx.x * blockDim.x + threadIdx.x;
    if (i < n4) {
        float4 v = ((const float4*)in)[i];
        v.x = to_tf32(v.x); v.y = to_tf32(v.y);
        v.z = to_tf32(v.z); v.w = to_tf32(v.w);
        ((float4*)out)[i] = v;
    }
}

__global__ void transpose_round(const float* __restrict__ W, float* __restrict__ Wt,
                                int K, int N)   // W [K][N] -> Wt [N][K]
{
    __shared__ float t[32][33];
    int k0 = blockIdx.y * 32, n0 = blockIdx.x * 32;
    int x = threadIdx.x, y = threadIdx.y;   // block (32, 8)
    #pragma unroll
    for (int i = 0; i < 32; i += 8)
        t[y + i][x] = W[(size_t)(k0 + y + i) * N + n0 + x];
    __syncthreads();
    #pragma unroll
    for (int i = 0; i < 32; i += 8)
        Wt[(size_t)(n0 + y + i) * K + k0 + x] = to_tf32(t[x][y + i]);
}

// ---------------------------------------------------------------------------
// Flash attention, fp32 (unchanged; tf32-rounded ctx store for GEMM2)
// ---------------------------------------------------------------------------
#define QS_STRIDE 68
#define PS_STRIDE 65
#define FLASH_SMEM_FLOATS (64 * QS_STRIDE * 2 + 64 * PS_STRIDE + 64 * 64)
#define FLASH_SMEM_BYTES (FLASH_SMEM_FLOATS * 4)

__global__ __launch_bounds__(256) void flash_kernel()
{
    extern __shared__ float sm[];
    float* Qs = sm;                                        // [64][68]
    float* Ks = sm + 64 * QS_STRIDE;                       // [64][68]
    float* Ps = sm + 2 * 64 * QS_STRIDE;                   // [64][65]
    float* Vs = sm + 2 * 64 * QS_STRIDE + 64 * PS_STRIDE;  // [64][64]

    int tid = threadIdx.x;
    int r = tid >> 2;
    int c = tid & 3;
    int bh = blockIdx.y;
    int qt = blockIdx.x;
    int q0 = qt * 64;
    size_t base = (size_t)bh * Tc;

    {
        int col = c * 16;
        const float4* src = (const float4*)(g_q + (base + q0 + r) * Dc + col);
        #pragma unroll
        for (int i = 0; i < 4; i++) {
            float4 f = src[i];
            f.x *= 0.125f; f.y *= 0.125f; f.z *= 0.125f; f.w *= 0.125f;
            *(float4*)&Qs[r * QS_STRIDE + col + i * 4] = f;
        }
    }

    float m_prev = -1e30f, lsum = 0.f;
    float4 o0 = make_float4(0.f, 0.f, 0.f, 0.f), o1 = o0, o2 = o0, o3 = o0;

    for (int kt = 0; kt <= qt; kt++) {
        __syncthreads();
        {
            int col = c * 16;
            const float4* ksrc = (const float4*)(g_k + (base + kt * 64 + r) * Dc + col);
            const float4* vsrc = (const float4*)(g_v + (base + kt * 64 + r) * Dc + col);
            #pragma unroll
            for (int i = 0; i < 4; i++) {
                *(float4*)&Ks[r * QS_STRIDE + col + i * 4] = ksrc[i];
                *(float4*)&Vs[r * 64 + col + i * 4] = vsrc[i];
            }
        }
        __syncthreads();

        float s[16];
        #pragma unroll
        for (int kk = 0; kk < 16; kk++) s[kk] = 0.f;
        #pragma unroll
        for (int d4 = 0; d4 < 16; d4++) {
            float4 q4 = *(const float4*)&Qs[r * QS_STRIDE + d4 * 4];
            #pragma unroll
            for (int kk = 0; kk < 16; kk++) {
                float4 k4 = *(const float4*)&Ks[(kk * 4 + c) * QS_STRIDE + d4 * 4];
                s[kk] = fmaf(q4.x, k4.x,
                        fmaf(q4.y, k4.y,
                        fmaf(q4.z, k4.z,
                        fmaf(q4.w, k4.w, s[kk]))));
            }
        }
        if (kt == qt) {
            #pragma unroll
            for (int kk = 0; kk < 16; kk++)
                if (kk * 4 + c > r) s[kk] = -1e30f;
        }

        float mt = s[0];
        #pragma unroll
        for (int kk = 1; kk < 16; kk++) mt = fmaxf(mt, s[kk]);
        mt = fmaxf(mt, __shfl_xor_sync(0xffffffffu, mt, 1));
        mt = fmaxf(mt, __shfl_xor_sync(0xffffffffu, mt, 2));
        float m_new = fmaxf(m_prev, mt);
        float alpha = __expf(m_prev - m_new);

        float rs = 0.f;
        #pragma unroll
        for (int kk = 0; kk < 16; kk++) {
            float p = __expf(s[kk] - m_new);
            Ps[r * PS_STRIDE + kk * 4 + c] = p;
            rs += p;
        }
        rs += __shfl_xor_sync(0xffffffffu, rs, 1);
        rs += __shfl_xor_sync(0xffffffffu, rs, 2);
        lsum = lsum * alpha + rs;
        m_prev = m_new;

        o0.x *= alpha; o0.y *= alpha; o0.z *= alpha; o0.w *= alpha;
        o1.x *= alpha; o1.y *= alpha; o1.z *= alpha; o1.w *= alpha;
        o2.x *= alpha; o2.y *= alpha; o2.z *= alpha; o2.w *= alpha;
        o3.x *= alpha; o3.y *= alpha; o3.z *= alpha; o3.w *= alpha;
        __syncwarp();

        #pragma unroll 16
        for (int k = 0; k < 64; k++) {
            float pv = Ps[r * PS_STRIDE + k];
            float4 v0 = *(const float4*)&Vs[k * 64 + 0  + c * 4];
            float4 v1 = *(const float4*)&Vs[k * 64 + 16 + c * 4];
            float4 v2 = *(const float4*)&Vs[k * 64 + 32 + c * 4];
            float4 v3 = *(const float4*)&Vs[k * 64 + 48 + c * 4];
            o0.x = fmaf(pv, v0.x, o0.x); o0.y = fmaf(pv, v0.y, o0.y);
            o0.z = fmaf(pv, v0.z, o0.z); o0.w = fmaf(pv, v0.w, o0.w);
            o1.x = fmaf(pv, v1.x, o1.x); o1.y = fmaf(pv, v1.y, o1.y);
            o1.z = fmaf(pv, v1.z, o1.z); o1.w = fmaf(pv, v1.w, o1.w);
            o2.x = fmaf(pv, v2.x, o2.x); o2.y = fmaf(pv, v2.y, o2.y);
            o2.z = fmaf(pv, v2.z, o2.z); o2.w = fmaf(pv, v2.w, o2.w);
            o3.x = fmaf(pv, v3.x, o3.x); o3.y = fmaf(pv, v3.y, o3.y);
            o3.z = fmaf(pv, v3.z, o3.z); o3.w = fmaf(pv, v3.w, o3.w);
        }
    }

    float inv = 1.f / lsum;
    int b = bh >> 4, h = bh & 15;
    float* outp = g_ctx + ((size_t)(b * Tc + q0 + r)) * Ec + h * Dc;
    float ov[16] = {o0.x*inv, o0.y*inv, o0.z*inv, o0.w*inv,
                    o1.x*inv, o1.y*inv, o1.z*inv, o1.w*inv,
                    o2.x*inv, o2.y*inv, o2.z*inv, o2.w*inv,
                    o3.x*inv, o3.y*inv, o3.z*inv, o3.w*inv};
    #pragma unroll
    for (int i = 0; i < 16; i++) ov[i] = to_tf32(ov[i]);
    *(float4*)&outp[0  + c * 4] = make_float4(ov[0],  ov[1],  ov[2],  ov[3]);
    *(float4*)&outp[16 + c * 4] = make_float4(ov[4],  ov[5],  ov[6],  ov[7]);
    *(float4*)&outp[32 + c * 4] = make_float4(ov[8],  ov[9],  ov[10], ov[11]);
    *(float4*)&outp[48 + c * 4] = make_float4(ov[12], ov[13], ov[14], ov[15]);
}

// ---------------------------------------------------------------------------
extern "C" void kernel_launch(void* const* d_in, const int* in_sizes, int n_in,
                              void* d_out, int out_size)
{
    const float* x     = (const float*)d_in[0];   // [4,2048,1024]
    const float* w_qkv = (const float*)d_in[1];   // [1024,3072]
    const float* b_qkv = (const float*)d_in[2];   // [3072]
    const float* w_out = (const float*)d_in[3];   // [1024,1024]
    const float* b_out = (const float*)d_in[4];   // [1024]
    float* out = (float*)d_out;                   // [4,2048,1024]

    (void)in_sizes; (void)n_in; (void)out_size;

    cudaFuncSetAttribute((const void*)flash_kernel,
                         cudaFuncAttributeMaxDynamicSharedMemorySize, FLASH_SMEM_BYTES);

    float* xr    = nullptr;  cudaGetSymbolAddress((void**)&xr,    g_xr);
    float* wqkvT = nullptr;  cudaGetSymbolAddress((void**)&wqkvT, g_wqkvT);
    float* woutT = nullptr;  cudaGetSymbolAddress((void**)&woutT, g_woutT);
    float* ctx   = nullptr;  cudaGetSymbolAddress((void**)&ctx,   g_ctx);

    // Pre-pass: tf32 rounding + weight transposes
    {
        int n4 = MROWS * Ec / 4;
        round_tf32_vec<<<(n4 + 255) / 256, 256>>>(x, xr, n4);
        dim3 tb(32, 8);
        transpose_round<<<dim3(3 * Ec / 32, Ec / 32), tb>>>(w_qkv, wqkvT, Ec, 3 * Ec);
        transpose_round<<<dim3(Ec / 32, Ec / 32), tb>>>(w_out, woutT, Ec, Ec);
    }
    // Stage 1: QKV projection (tf32 mma.sync) -> g_q/g_k/g_v in [B,H,T,D]
    {
        dim3 grid(3 * Ec / 128, MROWS / 128);   // (24, 64)
        tc_gemm<0><<<grid, 256>>>(xr, wqkvT, b_qkv, nullptr, MROWS, 3 * Ec, Ec);
    }
    // Stage 2: causal flash attention -> g_ctx (tf32-rounded)
    {
        dim3 grid(Tc / 64, Bc * Hc);            // (32, 64)
        flash_kernel<<<grid, 256, FLASH_SMEM_BYTES>>>();
    }
    // Stage 3: output projection (tf32 mma.sync) -> d_out
    {
        dim3 grid(Ec / 128, MROWS / 128);       // (8, 64)
        tc_gemm<1><<<grid, 256>>>(ctx, woutT, b_out, out, MROWS, Ec, Ec);
    }
}

// round 5
// speedup vs baseline: 4.0881x; 3.2146x over previous
#include <cuda_runtime.h>
#include <cstdint>

#define Bc 4
#define Tc 2048
#define Ec 1024
#define Hc 16
#define Dc 64
#define MROWS (Bc * Tc)   // 8192

__device__ float g_q[(size_t)Bc * Hc * Tc * Dc];
__device__ float g_k[(size_t)Bc * Hc * Tc * Dc];
__device__ float g_v[(size_t)Bc * Hc * Tc * Dc];
__device__ float g_ctx[(size_t)MROWS * Ec];
__device__ float g_xr[(size_t)MROWS * Ec];
__device__ float g_wqkvT[(size_t)3 * Ec * Ec];
__device__ float g_woutT[(size_t)Ec * Ec];

// ---------------------------------------------------------------------------
__device__ __forceinline__ uint32_t smem_u32(const void* p) {
    uint32_t a;
    asm("{ .reg .u64 t; cvta.to.shared.u64 t, %1; cvt.u32.u64 %0, t; }"
        : "=r"(a) : "l"(p));
    return a;
}
__device__ __forceinline__ float to_tf32(float x) {
    uint32_t r;
    asm("cvt.rna.tf32.f32 %0, %1;" : "=r"(r) : "f"(x));
    return __uint_as_float(r);
}
__device__ __forceinline__ float ex2(float x) {
    float r;
    asm("ex2.approx.f32 %0, %1;" : "=f"(r) : "f"(x));
    return r;
}
__device__ __forceinline__ void cp16(uint32_t saddr, const float* g) {
    asm volatile("cp.async.cg.shared.global [%0], [%1], 16;"
                 :: "r"(saddr), "l"(__cvta_generic_to_global(g)) : "memory");
}
__device__ __forceinline__ void cp_commit() {
    asm volatile("cp.async.commit_group;" ::: "memory");
}
template <int N>
__device__ __forceinline__ void cp_wait() {
    asm volatile("cp.async.wait_group %0;" :: "n"(N) : "memory");
}
__device__ __forceinline__ void mma168(float* c, const uint32_t* a, const uint32_t* b) {
    asm volatile(
        "mma.sync.aligned.m16n8k8.row.col.f32.tf32.tf32.f32 "
        "{%0,%1,%2,%3}, {%4,%5,%6,%7}, {%8,%9}, {%0,%1,%2,%3};"
        : "+f"(c[0]), "+f"(c[1]), "+f"(c[2]), "+f"(c[3])
        : "r"(a[0]), "r"(a[1]), "r"(a[2]), "r"(a[3]), "r"(b[0]), "r"(b[1]));
}
__device__ __forceinline__ void mma168f(float* c, const float* a, const float* b) {
    uint32_t au[4] = {__float_as_uint(a[0]), __float_as_uint(a[1]),
                      __float_as_uint(a[2]), __float_as_uint(a[3])};
    uint32_t bu[2] = {__float_as_uint(b[0]), __float_as_uint(b[1])};
    mma168(c, au, bu);
}

// ---------------------------------------------------------------------------
// tc_gemm (unchanged from R4 except MODE0 epilogue rounds to tf32)
// ---------------------------------------------------------------------------
#define BK 16
#define SA 20

template <int MODE>
__global__ __launch_bounds__(256) void tc_gemm(
    const float* __restrict__ A, const float* __restrict__ Bt,
    const float* __restrict__ bias, float* __restrict__ C,
    int M, int N, int K)
{
    __shared__ float smA[2][128 * SA];
    __shared__ float smB[2][128 * SA];

    int tid = threadIdx.x;
    int lane = tid & 31;
    int warp = tid >> 5;
    int warpM = warp >> 2;
    int warpN = warp & 3;
    int g  = lane >> 2;
    int tg = lane & 3;

    int mBase = blockIdx.y * 128;
    int nBase = blockIdx.x * 128;
    const int KT = K >> 4;

    uint32_t sA[2] = { smem_u32(&smA[0][0]), smem_u32(&smA[1][0]) };
    uint32_t sB[2] = { smem_u32(&smB[0][0]), smem_u32(&smB[1][0]) };

    auto load_tile = [&](int p, int kt) {
        #pragma unroll
        for (int i = 0; i < 4; i++) {
            int idx = tid + i * 256;
            int row = (idx >> 2) & 127;
            int seg = idx & 3;
            if (idx < 512)
                cp16(sA[p] + row * (SA * 4) + seg * 16,
                     A + (size_t)(mBase + row) * K + kt * BK + seg * 4);
            else
                cp16(sB[p] + row * (SA * 4) + seg * 16,
                     Bt + (size_t)(nBase + row) * K + kt * BK + seg * 4);
        }
        cp_commit();
    };

    float acc[4][4][4] = {};

    load_tile(0, 0);
    load_tile(1, 1);

    for (int kt = 0; kt < KT; kt++) {
        int p = kt & 1;
        if (kt + 1 < KT) cp_wait<1>(); else cp_wait<0>();
        __syncthreads();

        #pragma unroll
        for (int ks = 0; ks < 2; ks++) {
            uint32_t a[4][4], b[4][2];
            const float* Ab = &smA[p][(warpM * 64 + g) * SA + ks * 8 + tg];
            #pragma unroll
            for (int i = 0; i < 4; i++) {
                a[i][0] = __float_as_uint(Ab[(i * 16) * SA]);
                a[i][1] = __float_as_uint(Ab[(i * 16 + 8) * SA]);
                a[i][2] = __float_as_uint(Ab[(i * 16) * SA + 4]);
                a[i][3] = __float_as_uint(Ab[(i * 16 + 8) * SA + 4]);
            }
            const float* Bb = &smB[p][(warpN * 32 + g) * SA + ks * 8 + tg];
            #pragma unroll
            for (int j = 0; j < 4; j++) {
                b[j][0] = __float_as_uint(Bb[(j * 8) * SA]);
                b[j][1] = __float_as_uint(Bb[(j * 8) * SA + 4]);
            }
            #pragma unroll
            for (int i = 0; i < 4; i++)
                #pragma unroll
                for (int j = 0; j < 4; j++)
                    mma168(acc[i][j], a[i], b[j]);
        }
        __syncthreads();

        if (kt + 2 < KT) load_tile(p, kt + 2);
    }

    #pragma unroll
    for (int i = 0; i < 4; i++) {
        #pragma unroll
        for (int j = 0; j < 4; j++) {
            int row = mBase + warpM * 64 + i * 16 + g;
            int col = nBase + warpN * 32 + j * 8 + 2 * tg;
            float2 bb = *(const float2*)&bias[col];
            float2 v0, v1;
            if (MODE == 0) {   // round q/k/v to tf32 at source for MMA flash
                v0 = make_float2(to_tf32(acc[i][j][0] + bb.x), to_tf32(acc[i][j][1] + bb.y));
                v1 = make_float2(to_tf32(acc[i][j][2] + bb.x), to_tf32(acc[i][j][3] + bb.y));
            } else {
                v0 = make_float2(acc[i][j][0] + bb.x, acc[i][j][1] + bb.y);
                v1 = make_float2(acc[i][j][2] + bb.x, acc[i][j][3] + bb.y);
            }
            if (MODE == 0) {
                int part = col >> 10;
                int e = col & 1023;
                int h = e >> 6;
                int d = e & 63;
                float* base = ((part == 0) ? g_q : (part == 1) ? g_k : g_v);
                int b0 = row >> 11, t0 = row & 2047;
                *(float2*)&base[(((size_t)b0 * Hc + h) * Tc + t0) * Dc + d] = v0;
                int r1 = row + 8;
                int b1 = r1 >> 11, t1 = r1 & 2047;
                *(float2*)&base[(((size_t)b1 * Hc + h) * Tc + t1) * Dc + d] = v1;
            } else {
                *(float2*)&C[(size_t)row * N + col] = v0;
                *(float2*)&C[(size_t)(row + 8) * N + col] = v1;
            }
        }
    }
}

// ---------------------------------------------------------------------------
__global__ void round_tf32_vec(const float* __restrict__ in, float* __restrict__ out, int n4)
{
    int i = blockIdx.x * blockDim.x + threadIdx.x;
    if (i < n4) {
        float4 v = ((const float4*)in)[i];
        v.x = to_tf32(v.x); v.y = to_tf32(v.y);
        v.z = to_tf32(v.z); v.w = to_tf32(v.w);
        ((float4*)out)[i] = v;
    }
}

__global__ void transpose_round(const float* __restrict__ W, float* __restrict__ Wt,
                                int K, int N)
{
    __shared__ float t[32][33];
    int k0 = blockIdx.y * 32, n0 = blockIdx.x * 32;
    int x = threadIdx.x, y = threadIdx.y;
    #pragma unroll
    for (int i = 0; i < 32; i += 8)
        t[y + i][x] = W[(size_t)(k0 + y + i) * N + n0 + x];
    __syncthreads();
    #pragma unroll
    for (int i = 0; i < 32; i += 8)
        Wt[(size_t)(n0 + y + i) * K + k0 + x] = to_tf32(t[x][y + i]);
}

// ---------------------------------------------------------------------------
// MMA flash attention (tf32). Block: 128 queries x one bh. 8 warps x 16 rows.
// Q in registers (pre-scaled by 0.125*log2e, exp2-domain softmax).
// K/V 64-key tiles double-buffered via cp.async, stride-68 smem.
// P stays in registers: acc->A-frag conversion via shfl.idx.
// ---------------------------------------------------------------------------
#define FS 68
#define FTILE (64 * FS)                   // floats per K or V tile
#define FBUF (2 * FTILE)                  // K+V per buffer
#define FLASH_SMEM_BYTES (2 * FBUF * 4)   // 69632 B

#define QSCALE 0.18033688011112042f       // 0.125 * log2(e)

__global__ __launch_bounds__(256) void flash_mma()
{
    extern __shared__ float fs[];

    int tid = threadIdx.x;
    int lane = tid & 31;
    int w = tid >> 5;
    int g = lane >> 2;
    int tg = lane & 3;

    int qt = (gridDim.x - 1) - blockIdx.x;   // heavy blocks first
    int q0 = qt * 128;
    int bh = blockIdx.y;
    size_t gbase = (size_t)bh * Tc * Dc;

    int r0 = q0 + w * 16 + g;
    int r1 = r0 + 8;

    // Q fragments (row-major A): qf[ks] = {Q[r0][8ks+tg], Q[r1][8ks+tg],
    //                                      Q[r0][8ks+tg+4], Q[r1][8ks+tg+4]}
    float qf[8][4];
    {
        const float* Q0 = g_q + gbase + (size_t)r0 * Dc;
        const float* Q1 = g_q + gbase + (size_t)r1 * Dc;
        #pragma unroll
        for (int ks = 0; ks < 8; ks++) {
            qf[ks][0] = to_tf32(Q0[ks * 8 + tg] * QSCALE);
            qf[ks][1] = to_tf32(Q1[ks * 8 + tg] * QSCALE);
            qf[ks][2] = to_tf32(Q0[ks * 8 + tg + 4] * QSCALE);
            qf[ks][3] = to_tf32(Q1[ks * 8 + tg + 4] * QSCALE);
        }
    }

    float oacc[8][4] = {};
    float m0 = -1e30f, m1 = -1e30f, l0 = 0.f, l1 = 0.f;

    const int nT = 2 * qt + 2;

    auto load_tile = [&](int p, int kt) {
        float* kb = fs + p * FBUF;
        float* vb = kb + FTILE;
        const float* Kg = g_k + gbase + (size_t)kt * 64 * Dc;
        const float* Vg = g_v + gbase + (size_t)kt * 64 * Dc;
        #pragma unroll
        for (int i = 0; i < 4; i++) {
            int idx = tid + i * 256;     // 0..1023
            int row = idx >> 4;
            int seg = idx & 15;
            cp16(smem_u32(kb + row * FS + seg * 4), Kg + row * Dc + seg * 4);
            cp16(smem_u32(vb + row * FS + seg * 4), Vg + row * Dc + seg * 4);
        }
        cp_commit();
    };

    load_tile(0, 0);
    load_tile(1, 1);

    for (int kt = 0; kt < nT; kt++) {
        int p = kt & 1;
        if (kt + 1 < nT) cp_wait<1>(); else cp_wait<0>();
        __syncthreads();

        const float* kb = fs + p * FBUF;
        const float* vb = kb + FTILE;
        int k0 = kt * 64;

        // ---- S = Q @ K^T (exp2 domain, scale folded into Q) ----
        float sacc[8][4] = {};
        #pragma unroll
        for (int ks = 0; ks < 8; ks++) {
            #pragma unroll
            for (int j = 0; j < 8; j++) {
                float b[2];
                b[0] = kb[(j * 8 + g) * FS + ks * 8 + tg];
                b[1] = kb[(j * 8 + g) * FS + ks * 8 + tg + 4];
                mma168f(sacc[j], qf[ks], b);
            }
        }

        // ---- causal mask (only diagonal-overlapping tiles) ----
        if (k0 + 63 > r0) {
            #pragma unroll
            for (int j = 0; j < 8; j++) {
                int c = k0 + j * 8 + 2 * tg;
                if (c > r0)     sacc[j][0] = -1e30f;
                if (c + 1 > r0) sacc[j][1] = -1e30f;
                if (c > r1)     sacc[j][2] = -1e30f;
                if (c + 1 > r1) sacc[j][3] = -1e30f;
            }
        }

        // ---- streaming softmax ----
        float mt0 = -1e30f, mt1 = -1e30f;
        #pragma unroll
        for (int j = 0; j < 8; j++) {
            mt0 = fmaxf(mt0, fmaxf(sacc[j][0], sacc[j][1]));
            mt1 = fmaxf(mt1, fmaxf(sacc[j][2], sacc[j][3]));
        }
        mt0 = fmaxf(mt0, __shfl_xor_sync(0xffffffffu, mt0, 1));
        mt0 = fmaxf(mt0, __shfl_xor_sync(0xffffffffu, mt0, 2));
        mt1 = fmaxf(mt1, __shfl_xor_sync(0xffffffffu, mt1, 1));
        mt1 = fmaxf(mt1, __shfl_xor_sync(0xffffffffu, mt1, 2));

        float nm0 = fmaxf(m0, mt0);
        float nm1 = fmaxf(m1, mt1);
        float a0 = ex2(m0 - nm0);
        float a1 = ex2(m1 - nm1);
        m0 = nm0; m1 = nm1;

        float rs0 = 0.f, rs1 = 0.f;
        #pragma unroll
        for (int j = 0; j < 8; j++) {
            sacc[j][0] = to_tf32(ex2(sacc[j][0] - nm0));
            sacc[j][1] = to_tf32(ex2(sacc[j][1] - nm0));
            sacc[j][2] = to_tf32(ex2(sacc[j][2] - nm1));
            sacc[j][3] = to_tf32(ex2(sacc[j][3] - nm1));
            rs0 += sacc[j][0] + sacc[j][1];
            rs1 += sacc[j][2] + sacc[j][3];
        }
        rs0 += __shfl_xor_sync(0xffffffffu, rs0, 1);
        rs0 += __shfl_xor_sync(0xffffffffu, rs0, 2);
        rs1 += __shfl_xor_sync(0xffffffffu, rs1, 1);
        rs1 += __shfl_xor_sync(0xffffffffu, rs1, 2);
        l0 = l0 * a0 + rs0;
        l1 = l1 * a1 + rs1;

        #pragma unroll
        for (int j = 0; j < 8; j++) {
            oacc[j][0] *= a0; oacc[j][1] *= a0;
            oacc[j][2] *= a1; oacc[j][3] *= a1;
        }

        // ---- O += P @ V ----
        uint32_t src0 = (lane & ~3u) | (uint32_t)(tg >> 1);
        uint32_t src2 = src0 + 2;
        #pragma unroll
        for (int ks = 0; ks < 8; ks++) {
            float s00 = __shfl_sync(0xffffffffu, sacc[ks][0], src0);
            float s01 = __shfl_sync(0xffffffffu, sacc[ks][1], src0);
            float s10 = __shfl_sync(0xffffffffu, sacc[ks][2], src0);
            float s11 = __shfl_sync(0xffffffffu, sacc[ks][3], src0);
            float s20 = __shfl_sync(0xffffffffu, sacc[ks][0], src2);
            float s21 = __shfl_sync(0xffffffffu, sacc[ks][1], src2);
            float s30 = __shfl_sync(0xffffffffu, sacc[ks][2], src2);
            float s31 = __shfl_sync(0xffffffffu, sacc[ks][3], src2);
            float af[4];
            af[0] = (tg & 1) ? s01 : s00;
            af[1] = (tg & 1) ? s11 : s10;
            af[2] = (tg & 1) ? s21 : s20;
            af[3] = (tg & 1) ? s31 : s30;
            #pragma unroll
            for (int j = 0; j < 8; j++) {
                float b[2];
                b[0] = vb[(ks * 8 + tg) * FS + j * 8 + g];
                b[1] = vb[(ks * 8 + tg + 4) * FS + j * 8 + g];
                mma168f(oacc[j], af, b);
            }
        }

        __syncthreads();
        if (kt + 2 < nT) load_tile(p, kt + 2);
    }

    // ---- epilogue: normalize, round to tf32, store ctx ----
    float inv0 = 1.f / l0;
    float inv1 = 1.f / l1;
    int b = bh >> 4, h = bh & 15;
    float* o0p = g_ctx + ((size_t)b * Tc + r0) * Ec + h * Dc;
    float* o1p = g_ctx + ((size_t)b * Tc + r1) * Ec + h * Dc;
    #pragma unroll
    for (int j = 0; j < 8; j++) {
        int col = j * 8 + 2 * tg;
        *(float2*)&o0p[col] = make_float2(to_tf32(oacc[j][0] * inv0),
                                          to_tf32(oacc[j][1] * inv0));
        *(float2*)&o1p[col] = make_float2(to_tf32(oacc[j][2] * inv1),
                                          to_tf32(oacc[j][3] * inv1));
    }
}

// ---------------------------------------------------------------------------
extern "C" void kernel_launch(void* const* d_in, const int* in_sizes, int n_in,
                              void* d_out, int out_size)
{
    const float* x     = (const float*)d_in[0];
    const float* w_qkv = (const float*)d_in[1];
    const float* b_qkv = (const float*)d_in[2];
    const float* w_out = (const float*)d_in[3];
    const float* b_out = (const float*)d_in[4];
    float* out = (float*)d_out;

    (void)in_sizes; (void)n_in; (void)out_size;

    cudaFuncSetAttribute((const void*)flash_mma,
                         cudaFuncAttributeMaxDynamicSharedMemorySize, FLASH_SMEM_BYTES);

    float* xr    = nullptr;  cudaGetSymbolAddress((void**)&xr,    g_xr);
    float* wqkvT = nullptr;  cudaGetSymbolAddress((void**)&wqkvT, g_wqkvT);
    float* woutT = nullptr;  cudaGetSymbolAddress((void**)&woutT, g_woutT);
    float* ctx   = nullptr;  cudaGetSymbolAddress((void**)&ctx,   g_ctx);

    {
        int n4 = MROWS * Ec / 4;
        round_tf32_vec<<<(n4 + 255) / 256, 256>>>(x, xr, n4);
        dim3 tb(32, 8);
        transpose_round<<<dim3(3 * Ec / 32, Ec / 32), tb>>>(w_qkv, wqkvT, Ec, 3 * Ec);
        transpose_round<<<dim3(Ec / 32, Ec / 32), tb>>>(w_out, woutT, Ec, Ec);
    }
    {
        dim3 grid(3 * Ec / 128, MROWS / 128);
        tc_gemm<0><<<grid, 256>>>(xr, wqkvT, b_qkv, nullptr, MROWS, 3 * Ec, Ec);
    }
    {
        dim3 grid(Tc / 128, Bc * Hc);   // (16, 64)
        flash_mma<<<grid, 256, FLASH_SMEM_BYTES>>>();
    }
    {
        dim3 grid(Ec / 128, MROWS / 128);
        tc_gemm<1><<<grid, 256>>>(ctx, woutT, b_out, out, MROWS, Ec, Ec);
    }
}